// round 14
// baseline (speedup 1.0000x reference)
#include <cuda_runtime.h>
#include <cuda_fp16.h>

typedef unsigned int u32;

// ---------------- problem constants ----------------
#define NS    65536
#define KEXP  8
#define DIN   74
#define WID   64
#define DOUT  32
#define TILE  256
#define NT    512
#define MAXTILES (NS / TILE + KEXP)   // 264 <= 296 slots @2/SM -> single wave
#define NHB   256

// packed per-expert weight image:
// [0:8192)      W0H  [64 k][128B] swizzled
// [8192:10240)  W0HT [16 k][128B]
// [10240:10880) biases fp32: B0[64] B1[64] B2[32]
// [10880:19072) W1H  [64 k][128B]
// [19072:27264) W2H  [64 k][128B] (32 n -> 64B used)
#define WPACK_BYTES 27264
#define WP_PHASE1   10880
#define WP_PHASE2   16384

// ---------------- smem layout (bytes) ----------------
#define SM_XH0  0                  // X/H/G hi: [256 rows][128B] (k 0..63)
#define SM_XL0  32768
#define SM_XH1  65536              // X hi tail: [256 rows][48B] (k 64..79); phase2 overwrites
#define SM_XL1  77824
#define SM_W0H  90112              // phase1 image [W0H|W0HT|biases]
#define SM_W0HT 98304
#define SM_B0   100352
#define SM_B1   100608
#define SM_B2   100864
#define SM_SIDS 100992
#define SMEM_BYTES 102016          // 2 CTAs/SM (<= ~113.6KB each)
// phase2 overlay (XH1/XL1 dead after layer 0)
#define SM_W1H  65536
#define SM_W2H  73728

#define SWZ(off) ((off) ^ (((off) >> 3) & 0x70))

// ---------------- device scratch ----------------
__device__ int g_bhist[KEXP * NHB];
__device__ int g_bbase[KEXP * NHB];
__device__ int g_offs[KEXP + 1];
__device__ int g_order[NS];
__device__ __align__(16) char g_wpack[KEXP][WPACK_BYTES];

// ---------------- helpers ----------------
__device__ __forceinline__ u32 smem_u32(const void* p) {
    u32 a; asm("{ .reg .u64 t; cvta.to.shared.u64 t, %1; cvt.u32.u64 %0, t; }" : "=r"(a) : "l"(p));
    return a;
}
__device__ __forceinline__ void ldmA(u32 a[4], u32 addr) {
    asm volatile("ldmatrix.sync.aligned.m8n8.x4.shared.b16 {%0,%1,%2,%3}, [%4];"
                 : "=r"(a[0]), "=r"(a[1]), "=r"(a[2]), "=r"(a[3]) : "r"(addr));
}
__device__ __forceinline__ void ldmBT4(u32 b[4], u32 addr) {
    asm volatile("ldmatrix.sync.aligned.m8n8.x4.trans.shared.b16 {%0,%1,%2,%3}, [%4];"
                 : "=r"(b[0]), "=r"(b[1]), "=r"(b[2]), "=r"(b[3]) : "r"(addr));
}
__device__ __forceinline__ void mma16816(float c[4], const u32 a[4], const u32 b[2]) {
    asm volatile(
        "mma.sync.aligned.m16n8k16.row.col.f32.f16.f16.f32 "
        "{%0,%1,%2,%3}, {%4,%5,%6,%7}, {%8,%9}, {%0,%1,%2,%3};"
        : "+f"(c[0]), "+f"(c[1]), "+f"(c[2]), "+f"(c[3])
        : "r"(a[0]), "r"(a[1]), "r"(a[2]), "r"(a[3]), "r"(b[0]), "r"(b[1]));
}
__device__ __forceinline__ u32 hpack(__half a, __half b) {
    __half2 t(a, b);
    return *reinterpret_cast<u32*>(&t);
}
__device__ __forceinline__ void store_split(char* sm, u32 offH, u32 offL, float v0, float v1) {
    __half h0 = __float2half_rn(v0), h1 = __float2half_rn(v1);
    float l0 = v0 - __half2float(h0), l1 = v1 - __half2float(h1);
    *(u32*)(sm + offH) = hpack(h0, h1);
    *(u32*)(sm + offL) = hpack(__float2half_rn(l0), __float2half_rn(l1));
}
__device__ __forceinline__ void split4h(float4 v, u32& h01, u32& h23) {
    h01 = hpack(__float2half_rn(v.x), __float2half_rn(v.y));
    h23 = hpack(__float2half_rn(v.z), __float2half_rn(v.w));
}
__device__ __forceinline__ void cp16(u32 dst_smem, const void* src) {
    asm volatile("cp.async.ca.shared.global [%0], [%1], 16;" :: "r"(dst_smem), "l"(src) : "memory");
}

// ---------------- merged hist + weight pre-pack ----------------
__global__ void k_pre(const int* __restrict__ idxs,
                      const float* __restrict__ W0g, const float* __restrict__ b0g,
                      const float* __restrict__ W1g, const float* __restrict__ b1g,
                      const float* __restrict__ W2g, const float* __restrict__ b2g) {
    if (blockIdx.x < NHB) {
        __shared__ int sh[KEXP];
        if (threadIdx.x < KEXP) sh[threadIdx.x] = 0;
        __syncthreads();
        atomicAdd(&sh[idxs[blockIdx.x * 256 + threadIdx.x]], 1);
        __syncthreads();
        if (threadIdx.x < KEXP) g_bhist[threadIdx.x * NHB + blockIdx.x] = sh[threadIdx.x];
        return;
    }
    int pb = blockIdx.x - NHB;
    int e = pb >> 3;
    int vt = (pb & 7) * 256 + threadIdx.x;
    char* dst = g_wpack[e];

    const float4* W0e = (const float4*)(W0g + e * DIN * WID);
    for (int i = vt; i < 80 * 16; i += 2048) {
        int k = i >> 4, cq = i & 15;
        float4 v = (k < DIN) ? W0e[k * 16 + cq] : make_float4(0.f, 0.f, 0.f, 0.f);
        u32 h01, h23; split4h(v, h01, h23);
        u32 base = 0;
        if (k >= 64) { base = 8192; k -= 64; }
        u32 off = base + SWZ((u32)(k * 128 + cq * 8));
        *(u32*)(dst + off) = h01; *(u32*)(dst + off + 4) = h23;
    }
    const float4* W1e = (const float4*)(W1g + e * WID * WID);
    for (int i = vt; i < 64 * 16; i += 2048) {
        int k = i >> 4, cq = i & 15;
        float4 v = W1e[k * 16 + cq];
        u32 h01, h23; split4h(v, h01, h23);
        u32 off = 10880 + SWZ((u32)(k * 128 + cq * 8));
        *(u32*)(dst + off) = h01; *(u32*)(dst + off + 4) = h23;
    }
    const float4* W2e = (const float4*)(W2g + e * WID * DOUT);
    for (int i = vt; i < 64 * 8; i += 2048) {
        int k = i >> 3, cq = i & 7;
        float4 v = W2e[k * 8 + cq];
        u32 h01, h23; split4h(v, h01, h23);
        u32 off = 19072 + SWZ((u32)(k * 128 + cq * 8));
        *(u32*)(dst + off) = h01; *(u32*)(dst + off + 4) = h23;
    }
    float* bd = (float*)(dst + 10240);
    for (int i = vt; i < 160; i += 2048)
        bd[i] = (i < 64) ? b0g[e * WID + i]
              : (i < 128) ? b1g[e * WID + i - 64]
              : b2g[e * DOUT + i - 128];
}

// ---------------- scan ----------------
__global__ void k_scan() {
    __shared__ int tot[KEXP];
    __shared__ int offs[KEXP];
    int w = threadIdx.x >> 5, lane = threadIdx.x & 31;
    int carry = 0;
    int excl[8];
#pragma unroll
    for (int c = 0; c < 8; c++) {
        int v = g_bhist[w * NHB + c * 32 + lane];
        int s = v;
#pragma unroll
        for (int d = 1; d < 32; d <<= 1) {
            int t = __shfl_up_sync(0xFFFFFFFFu, s, d);
            if (lane >= d) s += t;
        }
        excl[c] = carry + s - v;
        carry += __shfl_sync(0xFFFFFFFFu, s, 31);
    }
    if (lane == 0) tot[w] = carry;
    __syncthreads();
    if (threadIdx.x == 0) {
        int a = 0;
        for (int e = 0; e < KEXP; e++) { offs[e] = a; g_offs[e] = a; a += tot[e]; }
        g_offs[KEXP] = a;
    }
    __syncthreads();
    int o = offs[w];
#pragma unroll
    for (int c = 0; c < 8; c++) g_bbase[w * NHB + c * 32 + lane] = o + excl[c];
}

// ---------------- scatter ----------------
__global__ void k_scatter(const int* __restrict__ idxs) {
    __shared__ int s_loc[KEXP];
    __shared__ int s_base[KEXP];
    if (threadIdx.x < KEXP) {
        s_loc[threadIdx.x] = 0;
        s_base[threadIdx.x] = g_bbase[threadIdx.x * NHB + blockIdx.x];
    }
    __syncthreads();
    int i = blockIdx.x * 256 + threadIdx.x;
    int e = idxs[i];
    int r = atomicAdd(&s_loc[e], 1);
    g_order[s_base[e] + r] = i;
}

// ---------------- fused MMA MLP kernel (TILE=256, 2 CTAs/SM, single wave) ----------------
__global__ void __launch_bounds__(NT, 2) k_mlp(
    const float* __restrict__ positions, const float* __restrict__ viewdirs,
    const float* __restrict__ features,
    float* __restrict__ out) {
    extern __shared__ char sm[];
    const u32 smb = smem_u32(sm);
    const int tid = threadIdx.x, lane = tid & 31, wid = tid >> 5;

    // blockIdx -> (expert, local tile)
    int e = -1, lt = 0;
    {
        int b = blockIdx.x, acc = 0;
#pragma unroll
        for (int i = 0; i < KEXP; i++) {
            int tiles = (g_offs[i + 1] - g_offs[i] + TILE - 1) / TILE;
            if (e < 0 && b < acc + tiles) { e = i; lt = b - acc; }
            acc += tiles;
        }
    }
    if (e < 0) return;
    const int base = g_offs[e] + lt * TILE;
    const int cnt = min(TILE, g_offs[e + 1] - base);

    int* sids = (int*)(sm + SM_SIDS);
    float* B0s = (float*)(sm + SM_B0);
    float* B1s = (float*)(sm + SM_B1);
    float* B2s = (float*)(sm + SM_B2);

    // ================= STAGING =================
    if (tid < TILE) {
        int n = g_order[base + min(tid, cnt - 1)];
        sids[tid] = n;
        const u32 rb = (u32)(tid * 128);
        const float4* f4 = (const float4*)(features + (size_t)n * 32);
#pragma unroll
        for (int i = 0; i < 8; i++) {
            float4 f = f4[i];
            u32 o0 = SWZ(rb + (u32)(8 * i));
            u32 o1 = SWZ(rb + (u32)(8 * i + 4));
            store_split(sm, SM_XH0 + o0, SM_XL0 + o0, f.x, f.y);
            store_split(sm, SM_XH0 + o1, SM_XL0 + o1, f.z, f.w);
        }
        {
            float p0 = positions[n * 3], p1 = positions[n * 3 + 1], p2 = positions[n * 3 + 2];
            float q0 = viewdirs[n * 3];
            float loc[16];
            loc[0] = p0; loc[1] = p1; loc[2] = p2;
#pragma unroll
            for (int s = 0; s < 2; s++) {
                float sc = (float)(1 << s);
                loc[3 + 3 * s] = __sinf(p0 * sc); loc[4 + 3 * s] = __sinf(p1 * sc); loc[5 + 3 * s] = __sinf(p2 * sc);
                loc[9 + 3 * s] = __cosf(p0 * sc); loc[10 + 3 * s] = __cosf(p1 * sc); loc[11 + 3 * s] = __cosf(p2 * sc);
            }
            loc[15] = q0;
#pragma unroll
            for (int j = 0; j < 8; j++) {
                u32 o = SWZ(rb + (u32)((32 + 2 * j) * 2));
                store_split(sm, SM_XH0 + o, SM_XL0 + o, loc[2 * j], loc[2 * j + 1]);
            }
        }
        {
            float q0 = viewdirs[n * 3], q1 = viewdirs[n * 3 + 1], q2 = viewdirs[n * 3 + 2];
            float loc[32];
            loc[0] = q1; loc[1] = q2;
#pragma unroll
            for (int s = 0; s < 4; s++) {
                float sc = (float)(1 << s);
                loc[2 + 3 * s] = __sinf(q0 * sc); loc[3 + 3 * s] = __sinf(q1 * sc); loc[4 + 3 * s] = __sinf(q2 * sc);
                loc[14 + 3 * s] = __cosf(q0 * sc); loc[15 + 3 * s] = __cosf(q1 * sc); loc[16 + 3 * s] = __cosf(q2 * sc);
            }
#pragma unroll
            for (int j = 26; j < 32; j++) loc[j] = 0.0f;
#pragma unroll
            for (int j = 0; j < 16; j++) {
                int k0 = 48 + 2 * j;
                if (k0 < 64) {
                    u32 o = SWZ(rb + (u32)(k0 * 2));
                    store_split(sm, SM_XH0 + o, SM_XL0 + o, loc[2 * j], loc[2 * j + 1]);
                } else {
                    u32 o = (u32)(tid * 48 + (k0 - 64) * 2);
                    store_split(sm, SM_XH1 + o, SM_XL1 + o, loc[2 * j], loc[2 * j + 1]);
                }
            }
        }
    } else {
        // phase-1 weight copy: W0 + biases (10880 B) by threads 256..511
        int t2 = tid - TILE;
        const char* src = g_wpack[e];
        for (int i = t2 * 16; i < WP_PHASE1; i += 256 * 16)
            cp16(smb + SM_W0H + i, src + i);
        asm volatile("cp.async.commit_group;" ::: "memory");
        asm volatile("cp.async.wait_group 0;" ::: "memory");
    }
    __syncthreads();

    // fragment lane coordinates (warp grid: 8 M-groups x 2 N-groups)
    const int wm = wid >> 1, wn = wid & 1;
    const int amat = lane >> 3, amr = lane & 7;
    const int arow_off = ((amat & 1) << 3) + amr;
    const int akoff = amat >> 1;
    const int bk = ((lane >> 3) & 1) * 8 + (lane & 7);
    const int bnh = (lane >> 4) * 8;
    const u32 bswz = ((u32)(bk & 7)) << 4;
    const u32 brow = (u32)(bk * 128);
    const u32 bcol0 = ((u32)((wn * 32 + bnh) * 2)) ^ bswz;
    const u32 bcol1 = ((u32)((wn * 32 + 16 + bnh) * 2)) ^ bswz;

    const int arow0 = wm * 32 + arow_off;        // mt=0 row
    const int arow1 = arow0 + 16;                // mt=1 row
    const u32 arb0 = (u32)(arow0 * 128), arb1 = (u32)(arow1 * 128);
    const int ar70 = arow0 & 7, ar71 = arow1 & 7;

    float C[2][4][4];

    // ================= LAYER 0 (K=80, N=64) — kt-outer, B hoisted =================
#pragma unroll
    for (int mt = 0; mt < 2; mt++)
#pragma unroll
        for (int nt = 0; nt < 4; nt++)
#pragma unroll
            for (int q = 0; q < 4; q++) C[mt][nt][q] = 0.0f;

#pragma unroll
    for (int kt = 0; kt < 5; kt++) {
        u32 ah[2][4], al[2][4], b0r[4], b1r[4];
        if (kt < 4) {
            u32 kx = (u32)(2 * kt + akoff);
            u32 o0 = arb0 + ((kx ^ ar70) << 4);
            u32 o1 = arb1 + ((kx ^ ar71) << 4);
            ldmA(ah[0], smb + SM_XH0 + o0); ldmA(al[0], smb + SM_XL0 + o0);
            ldmA(ah[1], smb + SM_XH0 + o1); ldmA(al[1], smb + SM_XL0 + o1);
            u32 bb = smb + SM_W0H + brow + kt * 2048;
            ldmBT4(b0r, bb + bcol0);
            ldmBT4(b1r, bb + bcol1);
        } else {
            u32 o0 = (u32)(arow0 * 48 + (akoff << 4));
            u32 o1 = (u32)(arow1 * 48 + (akoff << 4));
            ldmA(ah[0], smb + SM_XH1 + o0); ldmA(al[0], smb + SM_XL1 + o0);
            ldmA(ah[1], smb + SM_XH1 + o1); ldmA(al[1], smb + SM_XL1 + o1);
            u32 bb = smb + SM_W0HT + brow;
            ldmBT4(b0r, bb + bcol0);
            ldmBT4(b1r, bb + bcol1);
        }
#pragma unroll
        for (int mt = 0; mt < 2; mt++)
#pragma unroll
            for (int sub = 0; sub < 2; sub++) {
                mma16816(C[mt][sub], ah[mt], &b0r[2 * sub]);
                mma16816(C[mt][sub], al[mt], &b0r[2 * sub]);
                mma16816(C[mt][2 + sub], ah[mt], &b1r[2 * sub]);
                mma16816(C[mt][2 + sub], al[mt], &b1r[2 * sub]);
            }
    }
    __syncthreads();   // all warps done reading X(+tails) and W0

    // phase-2 weight copy (W1+W2 -> overlays dead XH1/XL1), overlapped with epilogue
    {
        const char* src = g_wpack[e] + WP_PHASE1;
#pragma unroll
        for (int i = tid * 16; i < WP_PHASE2; i += NT * 16)
            cp16(smb + SM_W1H + i, src + i);
        asm volatile("cp.async.commit_group;" ::: "memory");
    }

    // epilogue L0: bias+relu, split, write H into XH0/XL0
#pragma unroll
    for (int mt = 0; mt < 2; mt++)
#pragma unroll
        for (int nt = 0; nt < 4; nt++) {
            int row0 = wm * 32 + mt * 16 + (lane >> 2);
            int j0 = wn * 32 + nt * 8 + (lane & 3) * 2;
            float v0 = fmaxf(C[mt][nt][0] + B0s[j0], 0.0f);
            float v1 = fmaxf(C[mt][nt][1] + B0s[j0 + 1], 0.0f);
            float v2 = fmaxf(C[mt][nt][2] + B0s[j0], 0.0f);
            float v3 = fmaxf(C[mt][nt][3] + B0s[j0 + 1], 0.0f);
            u32 oa = SWZ((u32)(row0 * 128 + j0 * 2));
            u32 ob = SWZ((u32)((row0 + 8) * 128 + j0 * 2));
            store_split(sm, SM_XH0 + oa, SM_XL0 + oa, v0, v1);
            store_split(sm, SM_XH0 + ob, SM_XL0 + ob, v2, v3);
        }
    asm volatile("cp.async.wait_group 0;" ::: "memory");
    __syncthreads();

    // ================= LAYER 1 (K=64, N=64) =================
#pragma unroll
    for (int mt = 0; mt < 2; mt++)
#pragma unroll
        for (int nt = 0; nt < 4; nt++)
#pragma unroll
            for (int q = 0; q < 4; q++) C[mt][nt][q] = 0.0f;

#pragma unroll
    for (int kt = 0; kt < 4; kt++) {
        u32 ah[2][4], al[2][4], b0r[4], b1r[4];
        u32 kx = (u32)(2 * kt + akoff);
        u32 o0 = arb0 + ((kx ^ ar70) << 4);
        u32 o1 = arb1 + ((kx ^ ar71) << 4);
        ldmA(ah[0], smb + SM_XH0 + o0); ldmA(al[0], smb + SM_XL0 + o0);
        ldmA(ah[1], smb + SM_XH0 + o1); ldmA(al[1], smb + SM_XL0 + o1);
        u32 bb = smb + SM_W1H + brow + kt * 2048;
        ldmBT4(b0r, bb + bcol0);
        ldmBT4(b1r, bb + bcol1);
#pragma unroll
        for (int mt = 0; mt < 2; mt++)
#pragma unroll
            for (int sub = 0; sub < 2; sub++) {
                mma16816(C[mt][sub], ah[mt], &b0r[2 * sub]);
                mma16816(C[mt][sub], al[mt], &b0r[2 * sub]);
                mma16816(C[mt][2 + sub], ah[mt], &b1r[2 * sub]);
                mma16816(C[mt][2 + sub], al[mt], &b1r[2 * sub]);
            }
    }
    __syncthreads();   // done reading H before G overwrites the same panels

    // epilogue L1: bias+relu, split, write G into XH0/XL0
#pragma unroll
    for (int mt = 0; mt < 2; mt++)
#pragma unroll
        for (int nt = 0; nt < 4; nt++) {
            int row0 = wm * 32 + mt * 16 + (lane >> 2);
            int j0 = wn * 32 + nt * 8 + (lane & 3) * 2;
            float v0 = fmaxf(C[mt][nt][0] + B1s[j0], 0.0f);
            float v1 = fmaxf(C[mt][nt][1] + B1s[j0 + 1], 0.0f);
            float v2 = fmaxf(C[mt][nt][2] + B1s[j0], 0.0f);
            float v3 = fmaxf(C[mt][nt][3] + B1s[j0 + 1], 0.0f);
            u32 oa = SWZ((u32)(row0 * 128 + j0 * 2));
            u32 ob = SWZ((u32)((row0 + 8) * 128 + j0 * 2));
            store_split(sm, SM_XH0 + oa, SM_XL0 + oa, v0, v1);
            store_split(sm, SM_XH0 + ob, SM_XL0 + ob, v2, v3);
        }
    __syncthreads();

    // ================= LAYER 2 (K=64, N=32) =================
    const u32 bcol2 = ((u32)((wn * 16 + bnh) * 2)) ^ bswz;
#pragma unroll
    for (int mt = 0; mt < 2; mt++)
#pragma unroll
        for (int nt = 0; nt < 2; nt++)
#pragma unroll
            for (int q = 0; q < 4; q++) C[mt][nt][q] = 0.0f;

#pragma unroll
    for (int kt = 0; kt < 4; kt++) {
        u32 ah[2][4], al[2][4], br[4];
        u32 kx = (u32)(2 * kt + akoff);
        u32 o0 = arb0 + ((kx ^ ar70) << 4);
        u32 o1 = arb1 + ((kx ^ ar71) << 4);
        ldmA(ah[0], smb + SM_XH0 + o0); ldmA(al[0], smb + SM_XL0 + o0);
        ldmA(ah[1], smb + SM_XH0 + o1); ldmA(al[1], smb + SM_XL0 + o1);
        ldmBT4(br, smb + SM_W2H + brow + kt * 2048 + bcol2);
#pragma unroll
        for (int mt = 0; mt < 2; mt++)
#pragma unroll
            for (int sub = 0; sub < 2; sub++) {
                mma16816(C[mt][sub], ah[mt], &br[2 * sub]);
                mma16816(C[mt][sub], al[mt], &br[2 * sub]);
            }
    }

    // final epilogue: bias + shuffle-coalesced float4 scatter
#pragma unroll
    for (int mt = 0; mt < 2; mt++)
#pragma unroll
        for (int nt = 0; nt < 2; nt++) {
            int row0 = wm * 32 + mt * 16 + (lane >> 2);
            int q = lane & 3;
            int j0 = wn * 16 + nt * 8 + 2 * q;
            float a0 = C[mt][nt][0] + B2s[j0];
            float a1 = C[mt][nt][1] + B2s[j0 + 1];
            float b0 = C[mt][nt][2] + B2s[j0];
            float b1 = C[mt][nt][3] + B2s[j0 + 1];
            float pa0 = __shfl_xor_sync(0xFFFFFFFFu, a0, 1);
            float pa1 = __shfl_xor_sync(0xFFFFFFFFu, a1, 1);
            float pb0 = __shfl_xor_sync(0xFFFFFFFFu, b0, 1);
            float pb1 = __shfl_xor_sync(0xFFFFFFFFu, b1, 1);
            if (!(q & 1)) {
                int colb = wn * 16 + nt * 8 + 2 * q;
                if (row0 < cnt)
                    *(float4*)(out + (size_t)sids[row0] * DOUT + colb) =
                        make_float4(a0, a1, pa0, pa1);
                if (row0 + 8 < cnt)
                    *(float4*)(out + (size_t)sids[row0 + 8] * DOUT + colb) =
                        make_float4(b0, b1, pb0, pb1);
            }
        }
}

// ---------------- launch ----------------
extern "C" void kernel_launch(void* const* d_in, const int* in_sizes, int n_in,
                              void* d_out, int out_size) {
    (void)in_sizes; (void)n_in; (void)out_size;
    const int*   idxs      = (const int*)d_in[0];
    const float* positions = (const float*)d_in[1];
    const float* viewdirs  = (const float*)d_in[2];
    const float* features  = (const float*)d_in[3];
    const float* W0 = (const float*)d_in[4];
    const float* b0 = (const float*)d_in[5];
    const float* W1 = (const float*)d_in[6];
    const float* b1 = (const float*)d_in[7];
    const float* W2 = (const float*)d_in[8];
    const float* b2 = (const float*)d_in[9];
    float* out = (float*)d_out;

    cudaFuncSetAttribute(k_mlp, cudaFuncAttributeMaxDynamicSharedMemorySize, SMEM_BYTES);

    k_pre<<<NHB + 64, 256>>>(idxs, W0, b0, W1, b1, W2, b2);
    k_scan<<<1, 256>>>();
    k_scatter<<<NHB, 256>>>(idxs);
    k_mlp<<<MAXTILES, NT, SMEM_BYTES>>>(positions, viewdirs, features, out);
}

// round 15
// speedup vs baseline: 1.0743x; 1.0743x over previous
#include <cuda_runtime.h>
#include <cuda_fp16.h>

typedef unsigned int u32;

// ---------------- problem constants ----------------
#define NS    65536
#define KEXP  8
#define DIN   74
#define WID   64
#define DOUT  32
#define TILE  128
#define NT    256
#define MAXTILES (NS / TILE + KEXP)   // 520 <= 592 slots @4/SM -> single wave
#define NHB   256

// packed per-expert weight image (hi+lo split):
// [0:8192)      W0H  [64 k][128B]   [8192:10240)  W0HT [16 k][128B]
// [10240:18432) W0L                 [18432:20480) W0LT
// [20480:21120) biases fp32: B0[64] B1[64] B2[32]
// [21120:29312) W1H   [29312:37504) W1L
// [37504:45696) W2H   [45696:53888) W2L
#define WPACK_BYTES 53888
#define WP_PH1      20480          // W0 hi+lo (contiguous)
#define WP_BIAS_OFF 20480
#define WP_PH2_OFF  21120
#define WP_PH2      32768          // W1 hi|lo + W2 hi|lo

// ---------------- smem layout (bytes) ----------------
#define SM_XH0  0                  // X/H/G fp16 (single panel): [128 rows][128B] (k 0..63)
#define SM_XT   16384              // X tail: [128 rows][48B] (k 64..79)
#define SM_W0H  22528              // phase1: W0H|W0HT|W0L|W0LT (lo = hi + 10240)
#define SM_W0HT 30720
#define SM_B0   49152
#define SM_B1   49408
#define SM_B2   49664
#define SM_SIDS 49792
#define SMEM_BYTES 50304           // 4 CTAs/SM
// phase2 overlay (X tail + W0 dead after layer 0): 16384..49152
#define SM_W1H  16384              // W1L = +8192
#define SM_W2H  32768              // W2L = +8192

#define SWZ(off) ((off) ^ (((off) >> 3) & 0x70))

// ---------------- device scratch ----------------
__device__ int g_bhist[KEXP * NHB];
__device__ int g_bbase[KEXP * NHB];
__device__ int g_offs[KEXP + 1];
__device__ int g_order[NS];
__device__ __align__(16) char g_wpack[KEXP][WPACK_BYTES];

// ---------------- helpers ----------------
__device__ __forceinline__ u32 smem_u32(const void* p) {
    u32 a; asm("{ .reg .u64 t; cvta.to.shared.u64 t, %1; cvt.u32.u64 %0, t; }" : "=r"(a) : "l"(p));
    return a;
}
__device__ __forceinline__ void ldmA(u32 a[4], u32 addr) {
    asm volatile("ldmatrix.sync.aligned.m8n8.x4.shared.b16 {%0,%1,%2,%3}, [%4];"
                 : "=r"(a[0]), "=r"(a[1]), "=r"(a[2]), "=r"(a[3]) : "r"(addr));
}
__device__ __forceinline__ void ldmBT4(u32 b[4], u32 addr) {
    asm volatile("ldmatrix.sync.aligned.m8n8.x4.trans.shared.b16 {%0,%1,%2,%3}, [%4];"
                 : "=r"(b[0]), "=r"(b[1]), "=r"(b[2]), "=r"(b[3]) : "r"(addr));
}
__device__ __forceinline__ void mma16816(float c[4], const u32 a[4], const u32 b[2]) {
    asm volatile(
        "mma.sync.aligned.m16n8k16.row.col.f32.f16.f16.f32 "
        "{%0,%1,%2,%3}, {%4,%5,%6,%7}, {%8,%9}, {%0,%1,%2,%3};"
        : "+f"(c[0]), "+f"(c[1]), "+f"(c[2]), "+f"(c[3])
        : "r"(a[0]), "r"(a[1]), "r"(a[2]), "r"(a[3]), "r"(b[0]), "r"(b[1]));
}
__device__ __forceinline__ u32 hpack(__half a, __half b) {
    __half2 t(a, b);
    return *reinterpret_cast<u32*>(&t);
}
// X: single fp16 store
__device__ __forceinline__ void store_h(char* sm, u32 off, float v0, float v1) {
    *(u32*)(sm + off) = hpack(__float2half_rn(v0), __float2half_rn(v1));
}
// W: hi/lo split of 4 consecutive values
__device__ __forceinline__ void split4hl(float4 v, u32& h01, u32& h23, u32& l01, u32& l23) {
    __half hx = __float2half_rn(v.x), hy = __float2half_rn(v.y);
    __half hz = __float2half_rn(v.z), hw = __float2half_rn(v.w);
    h01 = hpack(hx, hy); h23 = hpack(hz, hw);
    l01 = hpack(__float2half_rn(v.x - __half2float(hx)),
                __float2half_rn(v.y - __half2float(hy)));
    l23 = hpack(__float2half_rn(v.z - __half2float(hz)),
                __float2half_rn(v.w - __half2float(hw)));
}
__device__ __forceinline__ void cp16(u32 dst_smem, const void* src) {
    asm volatile("cp.async.ca.shared.global [%0], [%1], 16;" :: "r"(dst_smem), "l"(src) : "memory");
}

// ---------------- merged hist + weight pre-pack ----------------
__global__ void k_pre(const int* __restrict__ idxs,
                      const float* __restrict__ W0g, const float* __restrict__ b0g,
                      const float* __restrict__ W1g, const float* __restrict__ b1g,
                      const float* __restrict__ W2g, const float* __restrict__ b2g) {
    if (blockIdx.x < NHB) {
        __shared__ int sh[KEXP];
        if (threadIdx.x < KEXP) sh[threadIdx.x] = 0;
        __syncthreads();
        atomicAdd(&sh[idxs[blockIdx.x * 256 + threadIdx.x]], 1);
        __syncthreads();
        if (threadIdx.x < KEXP) g_bhist[threadIdx.x * NHB + blockIdx.x] = sh[threadIdx.x];
        return;
    }
    int pb = blockIdx.x - NHB;
    int e = pb >> 3;
    int vt = (pb & 7) * 256 + threadIdx.x;
    char* dst = g_wpack[e];

    const float4* W0e = (const float4*)(W0g + e * DIN * WID);
    for (int i = vt; i < 80 * 16; i += 2048) {
        int k = i >> 4, cq = i & 15;
        float4 v = (k < DIN) ? W0e[k * 16 + cq] : make_float4(0.f, 0.f, 0.f, 0.f);
        u32 h01, h23, l01, l23; split4hl(v, h01, h23, l01, l23);
        u32 base = 0;
        if (k >= 64) { base = 8192; k -= 64; }
        u32 off = base + SWZ((u32)(k * 128 + cq * 8));
        *(u32*)(dst + off) = h01;          *(u32*)(dst + off + 4) = h23;
        *(u32*)(dst + off + 10240) = l01;  *(u32*)(dst + off + 10244) = l23;
    }
    const float4* W1e = (const float4*)(W1g + e * WID * WID);
    for (int i = vt; i < 64 * 16; i += 2048) {
        int k = i >> 4, cq = i & 15;
        float4 v = W1e[k * 16 + cq];
        u32 h01, h23, l01, l23; split4hl(v, h01, h23, l01, l23);
        u32 off = 21120 + SWZ((u32)(k * 128 + cq * 8));
        *(u32*)(dst + off) = h01;         *(u32*)(dst + off + 4) = h23;
        *(u32*)(dst + off + 8192) = l01;  *(u32*)(dst + off + 8196) = l23;
    }
    const float4* W2e = (const float4*)(W2g + e * WID * DOUT);
    for (int i = vt; i < 64 * 8; i += 2048) {
        int k = i >> 3, cq = i & 7;
        float4 v = W2e[k * 8 + cq];
        u32 h01, h23, l01, l23; split4hl(v, h01, h23, l01, l23);
        u32 off = 37504 + SWZ((u32)(k * 128 + cq * 8));
        *(u32*)(dst + off) = h01;         *(u32*)(dst + off + 4) = h23;
        *(u32*)(dst + off + 8192) = l01;  *(u32*)(dst + off + 8196) = l23;
    }
    float* bd = (float*)(dst + WP_BIAS_OFF);
    for (int i = vt; i < 160; i += 2048)
        bd[i] = (i < 64) ? b0g[e * WID + i]
              : (i < 128) ? b1g[e * WID + i - 64]
              : b2g[e * DOUT + i - 128];
}

// ---------------- scan ----------------
__global__ void k_scan() {
    __shared__ int tot[KEXP];
    __shared__ int offs[KEXP];
    int w = threadIdx.x >> 5, lane = threadIdx.x & 31;
    int carry = 0;
    int excl[8];
#pragma unroll
    for (int c = 0; c < 8; c++) {
        int v = g_bhist[w * NHB + c * 32 + lane];
        int s = v;
#pragma unroll
        for (int d = 1; d < 32; d <<= 1) {
            int t = __shfl_up_sync(0xFFFFFFFFu, s, d);
            if (lane >= d) s += t;
        }
        excl[c] = carry + s - v;
        carry += __shfl_sync(0xFFFFFFFFu, s, 31);
    }
    if (lane == 0) tot[w] = carry;
    __syncthreads();
    if (threadIdx.x == 0) {
        int a = 0;
        for (int e = 0; e < KEXP; e++) { offs[e] = a; g_offs[e] = a; a += tot[e]; }
        g_offs[KEXP] = a;
    }
    __syncthreads();
    int o = offs[w];
#pragma unroll
    for (int c = 0; c < 8; c++) g_bbase[w * NHB + c * 32 + lane] = o + excl[c];
}

// ---------------- scatter ----------------
__global__ void k_scatter(const int* __restrict__ idxs) {
    __shared__ int s_loc[KEXP];
    __shared__ int s_base[KEXP];
    if (threadIdx.x < KEXP) {
        s_loc[threadIdx.x] = 0;
        s_base[threadIdx.x] = g_bbase[threadIdx.x * NHB + blockIdx.x];
    }
    __syncthreads();
    int i = blockIdx.x * 256 + threadIdx.x;
    int e = idxs[i];
    int r = atomicAdd(&s_loc[e], 1);
    g_order[s_base[e] + r] = i;
}

// ---------------- fused MMA MLP kernel (4 CTAs/SM, single wave, W-split) ----------------
__global__ void __launch_bounds__(NT, 4) k_mlp(
    const float* __restrict__ positions, const float* __restrict__ viewdirs,
    const float* __restrict__ features,
    float* __restrict__ out) {
    extern __shared__ char sm[];
    const u32 smb = smem_u32(sm);
    const int tid = threadIdx.x, lane = tid & 31, wid = tid >> 5;

    // blockIdx -> (expert, local tile)
    int e = -1, lt = 0;
    {
        int b = blockIdx.x, acc = 0;
#pragma unroll
        for (int i = 0; i < KEXP; i++) {
            int tiles = (g_offs[i + 1] - g_offs[i] + TILE - 1) / TILE;
            if (e < 0 && b < acc + tiles) { e = i; lt = b - acc; }
            acc += tiles;
        }
    }
    if (e < 0) return;
    const int base = g_offs[e] + lt * TILE;
    const int cnt = min(TILE, g_offs[e + 1] - base);

    int* sids = (int*)(sm + SM_SIDS);
    float* B0s = (float*)(sm + SM_B0);
    float* B1s = (float*)(sm + SM_B1);
    float* B2s = (float*)(sm + SM_B2);

    // ================= STAGING =================
    if (tid < TILE) {
        int n = g_order[base + min(tid, cnt - 1)];
        sids[tid] = n;
        const u32 rb = (u32)(tid * 128);
        const float4* f4 = (const float4*)(features + (size_t)n * 32);
#pragma unroll
        for (int i = 0; i < 8; i++) {
            float4 f = f4[i];
            store_h(sm, SM_XH0 + SWZ(rb + (u32)(8 * i)), f.x, f.y);
            store_h(sm, SM_XH0 + SWZ(rb + (u32)(8 * i + 4)), f.z, f.w);
        }
        {
            float p0 = positions[n * 3], p1 = positions[n * 3 + 1], p2 = positions[n * 3 + 2];
            float q0 = viewdirs[n * 3];
            float loc[16];
            loc[0] = p0; loc[1] = p1; loc[2] = p2;
#pragma unroll
            for (int s = 0; s < 2; s++) {
                float sc = (float)(1 << s);
                loc[3 + 3 * s] = __sinf(p0 * sc); loc[4 + 3 * s] = __sinf(p1 * sc); loc[5 + 3 * s] = __sinf(p2 * sc);
                loc[9 + 3 * s] = __cosf(p0 * sc); loc[10 + 3 * s] = __cosf(p1 * sc); loc[11 + 3 * s] = __cosf(p2 * sc);
            }
            loc[15] = q0;
#pragma unroll
            for (int j = 0; j < 8; j++)
                store_h(sm, SM_XH0 + SWZ(rb + (u32)((32 + 2 * j) * 2)), loc[2 * j], loc[2 * j + 1]);
        }
        {
            float q0 = viewdirs[n * 3], q1 = viewdirs[n * 3 + 1], q2 = viewdirs[n * 3 + 2];
            float loc[32];
            loc[0] = q1; loc[1] = q2;
#pragma unroll
            for (int s = 0; s < 4; s++) {
                float sc = (float)(1 << s);
                loc[2 + 3 * s] = __sinf(q0 * sc); loc[3 + 3 * s] = __sinf(q1 * sc); loc[4 + 3 * s] = __sinf(q2 * sc);
                loc[14 + 3 * s] = __cosf(q0 * sc); loc[15 + 3 * s] = __cosf(q1 * sc); loc[16 + 3 * s] = __cosf(q2 * sc);
            }
#pragma unroll
            for (int j = 26; j < 32; j++) loc[j] = 0.0f;
#pragma unroll
            for (int j = 0; j < 16; j++) {
                int k0 = 48 + 2 * j;
                if (k0 < 64)
                    store_h(sm, SM_XH0 + SWZ(rb + (u32)(k0 * 2)), loc[2 * j], loc[2 * j + 1]);
                else
                    store_h(sm, SM_XT + (u32)(tid * 48 + (k0 - 64) * 2), loc[2 * j], loc[2 * j + 1]);
            }
        }
    } else {
        // phase-1 weight copy: W0 hi+lo (20480 B) + biases (640 B)
        int t2 = tid - TILE;   // 0..127
        const char* src = g_wpack[e];
#pragma unroll
        for (int i = t2 * 16; i < WP_PH1; i += 128 * 16)
            cp16(smb + SM_W0H + i, src + i);
        if (t2 < 40) cp16(smb + SM_B0 + t2 * 16, src + WP_BIAS_OFF + t2 * 16);
        asm volatile("cp.async.commit_group;" ::: "memory");
        asm volatile("cp.async.wait_group 0;" ::: "memory");
    }
    __syncthreads();

    // fragment lane coordinates (warp grid: 4 M-groups x 2 N-groups)
    const int wm = wid >> 1, wn = wid & 1;
    const int amat = lane >> 3, amr = lane & 7;
    const int arow_off = ((amat & 1) << 3) + amr;
    const int akoff = amat >> 1;
    const int bk = ((lane >> 3) & 1) * 8 + (lane & 7);
    const int bnh = (lane >> 4) * 8;
    const u32 bswz = ((u32)(bk & 7)) << 4;
    const u32 brow = (u32)(bk * 128);
    const u32 bcol0 = ((u32)((wn * 32 + bnh) * 2)) ^ bswz;
    const u32 bcol1 = ((u32)((wn * 32 + 16 + bnh) * 2)) ^ bswz;

    const int arow0 = wm * 32 + arow_off;
    const int arow1 = arow0 + 16;
    const u32 arb0 = (u32)(arow0 * 128), arb1 = (u32)(arow1 * 128);
    const int ar70 = arow0 & 7, ar71 = arow1 & 7;

    float C[2][4][4];

    // ================= LAYER 0 (K=80, N=64) =================
#pragma unroll
    for (int mt = 0; mt < 2; mt++)
#pragma unroll
        for (int nt = 0; nt < 4; nt++)
#pragma unroll
            for (int q = 0; q < 4; q++) C[mt][nt][q] = 0.0f;

#pragma unroll
    for (int kt = 0; kt < 5; kt++) {
        u32 a[2][4];
        u32 wb;
        if (kt < 4) {
            u32 kx = (u32)(2 * kt + akoff);
            u32 o0 = arb0 + ((kx ^ ar70) << 4);
            u32 o1 = arb1 + ((kx ^ ar71) << 4);
            ldmA(a[0], smb + SM_XH0 + o0);
            ldmA(a[1], smb + SM_XH0 + o1);
            wb = smb + SM_W0H + kt * 2048 + brow;
        } else {
            u32 o0 = (u32)(arow0 * 48 + (akoff << 4));
            u32 o1 = (u32)(arow1 * 48 + (akoff << 4));
            ldmA(a[0], smb + SM_XT + o0);
            ldmA(a[1], smb + SM_XT + o1);
            wb = smb + SM_W0HT + brow;
        }
#pragma unroll
        for (int np = 0; np < 2; np++) {
            u32 bh[4], bl[4];
            u32 addr = wb + (np ? bcol1 : bcol0);
            ldmBT4(bh, addr);
            ldmBT4(bl, addr + 10240);
#pragma unroll
            for (int mt = 0; mt < 2; mt++)
#pragma unroll
                for (int sub = 0; sub < 2; sub++) {
                    float* c = C[mt][2 * np + sub];
                    mma16816(c, a[mt], &bh[2 * sub]);
                    mma16816(c, a[mt], &bl[2 * sub]);
                }
        }
    }
    __syncthreads();   // all warps done reading X(+tail) and W0

    // phase-2 weight copy (W1 hi|lo + W2 hi|lo -> overlays dead XT/W0), overlapped with epilogue
    {
        const char* src = g_wpack[e] + WP_PH2_OFF;
#pragma unroll
        for (int i = tid * 16; i < WP_PH2; i += NT * 16)
            cp16(smb + SM_W1H + i, src + i);
        asm volatile("cp.async.commit_group;" ::: "memory");
    }

    // epilogue L0: bias+relu, fp16 store into XH0
#pragma unroll
    for (int mt = 0; mt < 2; mt++)
#pragma unroll
        for (int nt = 0; nt < 4; nt++) {
            int row0 = wm * 32 + mt * 16 + (lane >> 2);
            int j0 = wn * 32 + nt * 8 + (lane & 3) * 2;
            float v0 = fmaxf(C[mt][nt][0] + B0s[j0], 0.0f);
            float v1 = fmaxf(C[mt][nt][1] + B0s[j0 + 1], 0.0f);
            float v2 = fmaxf(C[mt][nt][2] + B0s[j0], 0.0f);
            float v3 = fmaxf(C[mt][nt][3] + B0s[j0 + 1], 0.0f);
            store_h(sm, SM_XH0 + SWZ((u32)(row0 * 128 + j0 * 2)), v0, v1);
            store_h(sm, SM_XH0 + SWZ((u32)((row0 + 8) * 128 + j0 * 2)), v2, v3);
        }
    asm volatile("cp.async.wait_group 0;" ::: "memory");
    __syncthreads();

    // ================= LAYER 1 (K=64, N=64) =================
#pragma unroll
    for (int mt = 0; mt < 2; mt++)
#pragma unroll
        for (int nt = 0; nt < 4; nt++)
#pragma unroll
            for (int q = 0; q < 4; q++) C[mt][nt][q] = 0.0f;

#pragma unroll
    for (int kt = 0; kt < 4; kt++) {
        u32 a[2][4];
        u32 kx = (u32)(2 * kt + akoff);
        u32 o0 = arb0 + ((kx ^ ar70) << 4);
        u32 o1 = arb1 + ((kx ^ ar71) << 4);
        ldmA(a[0], smb + SM_XH0 + o0);
        ldmA(a[1], smb + SM_XH0 + o1);
        u32 wb = smb + SM_W1H + kt * 2048 + brow;
#pragma unroll
        for (int np = 0; np < 2; np++) {
            u32 bh[4], bl[4];
            u32 addr = wb + (np ? bcol1 : bcol0);
            ldmBT4(bh, addr);
            ldmBT4(bl, addr + 8192);
#pragma unroll
            for (int mt = 0; mt < 2; mt++)
#pragma unroll
                for (int sub = 0; sub < 2; sub++) {
                    float* c = C[mt][2 * np + sub];
                    mma16816(c, a[mt], &bh[2 * sub]);
                    mma16816(c, a[mt], &bl[2 * sub]);
                }
        }
    }
    __syncthreads();   // done reading H before G overwrites the same panel

    // epilogue L1: bias+relu, fp16 store into XH0
#pragma unroll
    for (int mt = 0; mt < 2; mt++)
#pragma unroll
        for (int nt = 0; nt < 4; nt++) {
            int row0 = wm * 32 + mt * 16 + (lane >> 2);
            int j0 = wn * 32 + nt * 8 + (lane & 3) * 2;
            float v0 = fmaxf(C[mt][nt][0] + B1s[j0], 0.0f);
            float v1 = fmaxf(C[mt][nt][1] + B1s[j0 + 1], 0.0f);
            float v2 = fmaxf(C[mt][nt][2] + B1s[j0], 0.0f);
            float v3 = fmaxf(C[mt][nt][3] + B1s[j0 + 1], 0.0f);
            store_h(sm, SM_XH0 + SWZ((u32)(row0 * 128 + j0 * 2)), v0, v1);
            store_h(sm, SM_XH0 + SWZ((u32)((row0 + 8) * 128 + j0 * 2)), v2, v3);
        }
    __syncthreads();

    // ================= LAYER 2 (K=64, N=32) =================
    const u32 bcol2 = ((u32)((wn * 16 + bnh) * 2)) ^ bswz;
#pragma unroll
    for (int mt = 0; mt < 2; mt++)
#pragma unroll
        for (int nt = 0; nt < 2; nt++)
#pragma unroll
            for (int q = 0; q < 4; q++) C[mt][nt][q] = 0.0f;

#pragma unroll
    for (int kt = 0; kt < 4; kt++) {
        u32 a[2][4], bh[4], bl[4];
        u32 kx = (u32)(2 * kt + akoff);
        u32 o0 = arb0 + ((kx ^ ar70) << 4);
        u32 o1 = arb1 + ((kx ^ ar71) << 4);
        ldmA(a[0], smb + SM_XH0 + o0);
        ldmA(a[1], smb + SM_XH0 + o1);
        u32 addr = smb + SM_W2H + kt * 2048 + brow + bcol2;
        ldmBT4(bh, addr);
        ldmBT4(bl, addr + 8192);
#pragma unroll
        for (int mt = 0; mt < 2; mt++)
#pragma unroll
            for (int sub = 0; sub < 2; sub++) {
                float* c = C[mt][sub];
                mma16816(c, a[mt], &bh[2 * sub]);
                mma16816(c, a[mt], &bl[2 * sub]);
            }
    }

    // final epilogue: bias + shuffle-coalesced float4 scatter
#pragma unroll
    for (int mt = 0; mt < 2; mt++)
#pragma unroll
        for (int nt = 0; nt < 2; nt++) {
            int row0 = wm * 32 + mt * 16 + (lane >> 2);
            int q = lane & 3;
            int j0 = wn * 16 + nt * 8 + 2 * q;
            float a0 = C[mt][nt][0] + B2s[j0];
            float a1 = C[mt][nt][1] + B2s[j0 + 1];
            float b0 = C[mt][nt][2] + B2s[j0];
            float b1 = C[mt][nt][3] + B2s[j0 + 1];
            float pa0 = __shfl_xor_sync(0xFFFFFFFFu, a0, 1);
            float pa1 = __shfl_xor_sync(0xFFFFFFFFu, a1, 1);
            float pb0 = __shfl_xor_sync(0xFFFFFFFFu, b0, 1);
            float pb1 = __shfl_xor_sync(0xFFFFFFFFu, b1, 1);
            if (!(q & 1)) {
                int colb = wn * 16 + nt * 8 + 2 * q;
                if (row0 < cnt)
                    *(float4*)(out + (size_t)sids[row0] * DOUT + colb) =
                        make_float4(a0, a1, pa0, pa1);
                if (row0 + 8 < cnt)
                    *(float4*)(out + (size_t)sids[row0 + 8] * DOUT + colb) =
                        make_float4(b0, b1, pb0, pb1);
            }
        }
}

// ---------------- launch ----------------
extern "C" void kernel_launch(void* const* d_in, const int* in_sizes, int n_in,
                              void* d_out, int out_size) {
    (void)in_sizes; (void)n_in; (void)out_size;
    const int*   idxs      = (const int*)d_in[0];
    const float* positions = (const float*)d_in[1];
    const float* viewdirs  = (const float*)d_in[2];
    const float* features  = (const float*)d_in[3];
    const float* W0 = (const float*)d_in[4];
    const float* b0 = (const float*)d_in[5];
    const float* W1 = (const float*)d_in[6];
    const float* b1 = (const float*)d_in[7];
    const float* W2 = (const float*)d_in[8];
    const float* b2 = (const float*)d_in[9];
    float* out = (float*)d_out;

    cudaFuncSetAttribute(k_mlp, cudaFuncAttributeMaxDynamicSharedMemorySize, SMEM_BYTES);

    k_pre<<<NHB + 64, 256>>>(idxs, W0, b0, W1, b1, W2, b2);
    k_scan<<<1, 256>>>();
    k_scatter<<<NHB, 256>>>(idxs);
    k_mlp<<<MAXTILES, NT, SMEM_BYTES>>>(positions, viewdirs, features, out);
}

// round 16
// speedup vs baseline: 1.1620x; 1.0816x over previous
#include <cuda_runtime.h>
#include <cuda_fp16.h>

typedef unsigned int u32;

// ---------------- problem constants ----------------
#define NS    65536
#define KEXP  8
#define DIN   74
#define WID   64
#define DOUT  32
#define TILE  128
#define NT    256
#define MAXTILES (NS / TILE + KEXP)
#define NHB   256

// packed per-expert weight image (hi+lo split):
// [0:8192)      W0H  [64 k][128B]   [8192:10240)  W0HT [16 k][128B]
// [10240:18432) W0L                 [18432:20480) W0LT
// [20480:21120) biases fp32: B0[64] B1[64] B2[32]
// [21120:29312) W1H   [29312:37504) W1L
// [37504:45696) W2H   [45696:53888) W2L
#define WPACK_BYTES 53888
#define WP_PH1      20480
#define WP_BIAS_OFF 20480
#define WP_PH2_OFF  21120
#define WP_PH2      32768

// ---------------- smem layout (bytes) ----------------
#define SM_XH0  0                  // X/H/G fp16 (single panel): [128 rows][128B] (k 0..63)
#define SM_XT   16384              // X tail: [128 rows][48B] (k 64..79)
#define SM_W0H  22528              // phase1: W0H|W0HT|W0L|W0LT (lo = hi + 10240)
#define SM_W0HT 30720
#define SM_B0   49152
#define SM_B1   49408
#define SM_B2   49664
#define SM_SIDS 49792
#define SMEM_BYTES 50304
// phase2 overlay (X tail + W0 dead after layer 0)
#define SM_W1H  16384              // W1L = +8192
#define SM_W2H  32768              // W2L = +8192

#define SWZ(off) ((off) ^ (((off) >> 3) & 0x70))

// ---------------- device scratch ----------------
__device__ int g_bhist[KEXP * NHB];
__device__ int g_bbase[KEXP * NHB];
__device__ int g_offs[KEXP + 1];
__device__ int g_order[NS];
__device__ __align__(16) char g_wpack[KEXP][WPACK_BYTES];

// ---------------- helpers ----------------
__device__ __forceinline__ u32 smem_u32(const void* p) {
    u32 a; asm("{ .reg .u64 t; cvta.to.shared.u64 t, %1; cvt.u32.u64 %0, t; }" : "=r"(a) : "l"(p));
    return a;
}
__device__ __forceinline__ void ldmA(u32 a[4], u32 addr) {
    asm volatile("ldmatrix.sync.aligned.m8n8.x4.shared.b16 {%0,%1,%2,%3}, [%4];"
                 : "=r"(a[0]), "=r"(a[1]), "=r"(a[2]), "=r"(a[3]) : "r"(addr));
}
__device__ __forceinline__ void ldmBT4(u32 b[4], u32 addr) {
    asm volatile("ldmatrix.sync.aligned.m8n8.x4.trans.shared.b16 {%0,%1,%2,%3}, [%4];"
                 : "=r"(b[0]), "=r"(b[1]), "=r"(b[2]), "=r"(b[3]) : "r"(addr));
}
__device__ __forceinline__ void mma16816(float c[4], const u32 a[4], const u32 b[2]) {
    asm volatile(
        "mma.sync.aligned.m16n8k16.row.col.f32.f16.f16.f32 "
        "{%0,%1,%2,%3}, {%4,%5,%6,%7}, {%8,%9}, {%0,%1,%2,%3};"
        : "+f"(c[0]), "+f"(c[1]), "+f"(c[2]), "+f"(c[3])
        : "r"(a[0]), "r"(a[1]), "r"(a[2]), "r"(a[3]), "r"(b[0]), "r"(b[1]));
}
__device__ __forceinline__ u32 hpack(__half a, __half b) {
    __half2 t(a, b);
    return *reinterpret_cast<u32*>(&t);
}
__device__ __forceinline__ void store_h(char* sm, u32 off, float v0, float v1) {
    *(u32*)(sm + off) = hpack(__float2half_rn(v0), __float2half_rn(v1));
}
__device__ __forceinline__ void split4hl(float4 v, u32& h01, u32& h23, u32& l01, u32& l23) {
    __half hx = __float2half_rn(v.x), hy = __float2half_rn(v.y);
    __half hz = __float2half_rn(v.z), hw = __float2half_rn(v.w);
    h01 = hpack(hx, hy); h23 = hpack(hz, hw);
    l01 = hpack(__float2half_rn(v.x - __half2float(hx)),
                __float2half_rn(v.y - __half2float(hy)));
    l23 = hpack(__float2half_rn(v.z - __half2float(hz)),
                __float2half_rn(v.w - __half2float(hw)));
}
__device__ __forceinline__ void cp16(u32 dst_smem, const void* src) {
    asm volatile("cp.async.ca.shared.global [%0], [%1], 16;" :: "r"(dst_smem), "l"(src) : "memory");
}

// ---------------- merged hist + weight pre-pack ----------------
__global__ void k_pre(const int* __restrict__ idxs,
                      const float* __restrict__ W0g, const float* __restrict__ b0g,
                      const float* __restrict__ W1g, const float* __restrict__ b1g,
                      const float* __restrict__ W2g, const float* __restrict__ b2g) {
    if (blockIdx.x < NHB) {
        __shared__ int sh[KEXP];
        if (threadIdx.x < KEXP) sh[threadIdx.x] = 0;
        __syncthreads();
        atomicAdd(&sh[idxs[blockIdx.x * 256 + threadIdx.x]], 1);
        __syncthreads();
        if (threadIdx.x < KEXP) g_bhist[threadIdx.x * NHB + blockIdx.x] = sh[threadIdx.x];
        return;
    }
    int pb = blockIdx.x - NHB;
    int e = pb >> 3;
    int vt = (pb & 7) * 256 + threadIdx.x;
    char* dst = g_wpack[e];

    const float4* W0e = (const float4*)(W0g + e * DIN * WID);
    for (int i = vt; i < 80 * 16; i += 2048) {
        int k = i >> 4, cq = i & 15;
        float4 v = (k < DIN) ? W0e[k * 16 + cq] : make_float4(0.f, 0.f, 0.f, 0.f);
        u32 h01, h23, l01, l23; split4hl(v, h01, h23, l01, l23);
        u32 base = 0;
        if (k >= 64) { base = 8192; k -= 64; }
        u32 off = base + SWZ((u32)(k * 128 + cq * 8));
        *(u32*)(dst + off) = h01;          *(u32*)(dst + off + 4) = h23;
        *(u32*)(dst + off + 10240) = l01;  *(u32*)(dst + off + 10244) = l23;
    }
    const float4* W1e = (const float4*)(W1g + e * WID * WID);
    for (int i = vt; i < 64 * 16; i += 2048) {
        int k = i >> 4, cq = i & 15;
        float4 v = W1e[k * 16 + cq];
        u32 h01, h23, l01, l23; split4hl(v, h01, h23, l01, l23);
        u32 off = 21120 + SWZ((u32)(k * 128 + cq * 8));
        *(u32*)(dst + off) = h01;         *(u32*)(dst + off + 4) = h23;
        *(u32*)(dst + off + 8192) = l01;  *(u32*)(dst + off + 8196) = l23;
    }
    const float4* W2e = (const float4*)(W2g + e * WID * DOUT);
    for (int i = vt; i < 64 * 8; i += 2048) {
        int k = i >> 3, cq = i & 7;
        float4 v = W2e[k * 8 + cq];
        u32 h01, h23, l01, l23; split4hl(v, h01, h23, l01, l23);
        u32 off = 37504 + SWZ((u32)(k * 128 + cq * 8));
        *(u32*)(dst + off) = h01;         *(u32*)(dst + off + 4) = h23;
        *(u32*)(dst + off + 8192) = l01;  *(u32*)(dst + off + 8196) = l23;
    }
    float* bd = (float*)(dst + WP_BIAS_OFF);
    for (int i = vt; i < 160; i += 2048)
        bd[i] = (i < 64) ? b0g[e * WID + i]
              : (i < 128) ? b1g[e * WID + i - 64]
              : b2g[e * DOUT + i - 128];
}

// ---------------- scan ----------------
__global__ void k_scan() {
    __shared__ int tot[KEXP];
    __shared__ int offs[KEXP];
    int w = threadIdx.x >> 5, lane = threadIdx.x & 31;
    int carry = 0;
    int excl[8];
#pragma unroll
    for (int c = 0; c < 8; c++) {
        int v = g_bhist[w * NHB + c * 32 + lane];
        int s = v;
#pragma unroll
        for (int d = 1; d < 32; d <<= 1) {
            int t = __shfl_up_sync(0xFFFFFFFFu, s, d);
            if (lane >= d) s += t;
        }
        excl[c] = carry + s - v;
        carry += __shfl_sync(0xFFFFFFFFu, s, 31);
    }
    if (lane == 0) tot[w] = carry;
    __syncthreads();
    if (threadIdx.x == 0) {
        int a = 0;
        for (int e = 0; e < KEXP; e++) { offs[e] = a; g_offs[e] = a; a += tot[e]; }
        g_offs[KEXP] = a;
    }
    __syncthreads();
    int o = offs[w];
#pragma unroll
    for (int c = 0; c < 8; c++) g_bbase[w * NHB + c * 32 + lane] = o + excl[c];
}

// ---------------- scatter ----------------
__global__ void k_scatter(const int* __restrict__ idxs) {
    __shared__ int s_loc[KEXP];
    __shared__ int s_base[KEXP];
    if (threadIdx.x < KEXP) {
        s_loc[threadIdx.x] = 0;
        s_base[threadIdx.x] = g_bbase[threadIdx.x * NHB + blockIdx.x];
    }
    __syncthreads();
    int i = blockIdx.x * 256 + threadIdx.x;
    int e = idxs[i];
    int r = atomicAdd(&s_loc[e], 1);
    g_order[s_base[e] + r] = i;
}

// ---------------- fused MMA MLP kernel (3 CTAs/SM, ~85 regs, high-MLP loops) ----------------
__global__ void __launch_bounds__(NT, 3) k_mlp(
    const float* __restrict__ positions, const float* __restrict__ viewdirs,
    const float* __restrict__ features,
    float* __restrict__ out) {
    extern __shared__ char sm[];
    const u32 smb = smem_u32(sm);
    const int tid = threadIdx.x, lane = tid & 31, wid = tid >> 5;

    // blockIdx -> (expert, local tile)
    int e = -1, lt = 0;
    {
        int b = blockIdx.x, acc = 0;
#pragma unroll
        for (int i = 0; i < KEXP; i++) {
            int tiles = (g_offs[i + 1] - g_offs[i] + TILE - 1) / TILE;
            if (e < 0 && b < acc + tiles) { e = i; lt = b - acc; }
            acc += tiles;
        }
    }
    if (e < 0) return;
    const int base = g_offs[e] + lt * TILE;
    const int cnt = min(TILE, g_offs[e + 1] - base);

    int* sids = (int*)(sm + SM_SIDS);
    float* B0s = (float*)(sm + SM_B0);
    float* B1s = (float*)(sm + SM_B1);
    float* B2s = (float*)(sm + SM_B2);

    // ================= STAGING =================
    if (tid < TILE) {
        int n = g_order[base + min(tid, cnt - 1)];
        sids[tid] = n;
        const u32 rb = (u32)(tid * 128);
        const float4* f4 = (const float4*)(features + (size_t)n * 32);
#pragma unroll
        for (int i = 0; i < 8; i++) {
            float4 f = f4[i];
            store_h(sm, SM_XH0 + SWZ(rb + (u32)(8 * i)), f.x, f.y);
            store_h(sm, SM_XH0 + SWZ(rb + (u32)(8 * i + 4)), f.z, f.w);
        }
        {
            float p0 = positions[n * 3], p1 = positions[n * 3 + 1], p2 = positions[n * 3 + 2];
            float q0 = viewdirs[n * 3];
            float loc[16];
            loc[0] = p0; loc[1] = p1; loc[2] = p2;
#pragma unroll
            for (int s = 0; s < 2; s++) {
                float sc = (float)(1 << s);
                loc[3 + 3 * s] = __sinf(p0 * sc); loc[4 + 3 * s] = __sinf(p1 * sc); loc[5 + 3 * s] = __sinf(p2 * sc);
                loc[9 + 3 * s] = __cosf(p0 * sc); loc[10 + 3 * s] = __cosf(p1 * sc); loc[11 + 3 * s] = __cosf(p2 * sc);
            }
            loc[15] = q0;
#pragma unroll
            for (int j = 0; j < 8; j++)
                store_h(sm, SM_XH0 + SWZ(rb + (u32)((32 + 2 * j) * 2)), loc[2 * j], loc[2 * j + 1]);
        }
        {
            float q0 = viewdirs[n * 3], q1 = viewdirs[n * 3 + 1], q2 = viewdirs[n * 3 + 2];
            float loc[32];
            loc[0] = q1; loc[1] = q2;
#pragma unroll
            for (int s = 0; s < 4; s++) {
                float sc = (float)(1 << s);
                loc[2 + 3 * s] = __sinf(q0 * sc); loc[3 + 3 * s] = __sinf(q1 * sc); loc[4 + 3 * s] = __sinf(q2 * sc);
                loc[14 + 3 * s] = __cosf(q0 * sc); loc[15 + 3 * s] = __cosf(q1 * sc); loc[16 + 3 * s] = __cosf(q2 * sc);
            }
#pragma unroll
            for (int j = 26; j < 32; j++) loc[j] = 0.0f;
#pragma unroll
            for (int j = 0; j < 16; j++) {
                int k0 = 48 + 2 * j;
                if (k0 < 64)
                    store_h(sm, SM_XH0 + SWZ(rb + (u32)(k0 * 2)), loc[2 * j], loc[2 * j + 1]);
                else
                    store_h(sm, SM_XT + (u32)(tid * 48 + (k0 - 64) * 2), loc[2 * j], loc[2 * j + 1]);
            }
        }
    } else {
        // phase-1 weight copy: W0 hi+lo + biases
        int t2 = tid - TILE;
        const char* src = g_wpack[e];
#pragma unroll
        for (int i = t2 * 16; i < WP_PH1; i += 128 * 16)
            cp16(smb + SM_W0H + i, src + i);
        if (t2 < 40) cp16(smb + SM_B0 + t2 * 16, src + WP_BIAS_OFF + t2 * 16);
        asm volatile("cp.async.commit_group;" ::: "memory");
        asm volatile("cp.async.wait_group 0;" ::: "memory");
    }
    __syncthreads();

    // fragment lane coordinates (warp grid: 4 M-groups x 2 N-groups)
    const int wm = wid >> 1, wn = wid & 1;
    const int amat = lane >> 3, amr = lane & 7;
    const int arow_off = ((amat & 1) << 3) + amr;
    const int akoff = amat >> 1;
    const int bk = ((lane >> 3) & 1) * 8 + (lane & 7);
    const int bnh = (lane >> 4) * 8;
    const u32 bswz = ((u32)(bk & 7)) << 4;
    const u32 brow = (u32)(bk * 128);
    const u32 bcol0 = ((u32)((wn * 32 + bnh) * 2)) ^ bswz;
    const u32 bcol1 = ((u32)((wn * 32 + 16 + bnh) * 2)) ^ bswz;

    const int arow0 = wm * 32 + arow_off;
    const int arow1 = arow0 + 16;
    const u32 arb0 = (u32)(arow0 * 128), arb1 = (u32)(arow1 * 128);
    const int ar70 = arow0 & 7, ar71 = arow1 & 7;

    float C[2][4][4];

    // ================= LAYER 0 (K=80, N=64) — all 6 loads issued before 16 MMAs =================
#pragma unroll
    for (int mt = 0; mt < 2; mt++)
#pragma unroll
        for (int nt = 0; nt < 4; nt++)
#pragma unroll
            for (int q = 0; q < 4; q++) C[mt][nt][q] = 0.0f;

#pragma unroll
    for (int kt = 0; kt < 5; kt++) {
        u32 a[2][4], bh0[4], bl0[4], bh1[4], bl1[4];
        if (kt < 4) {
            u32 kx = (u32)(2 * kt + akoff);
            u32 o0 = arb0 + ((kx ^ ar70) << 4);
            u32 o1 = arb1 + ((kx ^ ar71) << 4);
            u32 wb = smb + SM_W0H + kt * 2048 + brow;
            ldmA(a[0], smb + SM_XH0 + o0);
            ldmA(a[1], smb + SM_XH0 + o1);
            ldmBT4(bh0, wb + bcol0);
            ldmBT4(bl0, wb + bcol0 + 10240);
            ldmBT4(bh1, wb + bcol1);
            ldmBT4(bl1, wb + bcol1 + 10240);
        } else {
            u32 o0 = (u32)(arow0 * 48 + (akoff << 4));
            u32 o1 = (u32)(arow1 * 48 + (akoff << 4));
            u32 wb = smb + SM_W0HT + brow;
            ldmA(a[0], smb + SM_XT + o0);
            ldmA(a[1], smb + SM_XT + o1);
            ldmBT4(bh0, wb + bcol0);
            ldmBT4(bl0, wb + bcol0 + 10240);
            ldmBT4(bh1, wb + bcol1);
            ldmBT4(bl1, wb + bcol1 + 10240);
        }
#pragma unroll
        for (int mt = 0; mt < 2; mt++)
#pragma unroll
            for (int sub = 0; sub < 2; sub++) {
                mma16816(C[mt][sub],     a[mt], &bh0[2 * sub]);
                mma16816(C[mt][2 + sub], a[mt], &bh1[2 * sub]);
            }
#pragma unroll
        for (int mt = 0; mt < 2; mt++)
#pragma unroll
            for (int sub = 0; sub < 2; sub++) {
                mma16816(C[mt][sub],     a[mt], &bl0[2 * sub]);
                mma16816(C[mt][2 + sub], a[mt], &bl1[2 * sub]);
            }
    }
    __syncthreads();   // all warps done reading X(+tail) and W0

    // phase-2 weight copy (W1 hi|lo + W2 hi|lo), overlapped with epilogue
    {
        const char* src = g_wpack[e] + WP_PH2_OFF;
#pragma unroll
        for (int i = tid * 16; i < WP_PH2; i += NT * 16)
            cp16(smb + SM_W1H + i, src + i);
        asm volatile("cp.async.commit_group;" ::: "memory");
    }

    // epilogue L0: bias+relu, fp16 store into XH0
#pragma unroll
    for (int mt = 0; mt < 2; mt++)
#pragma unroll
        for (int nt = 0; nt < 4; nt++) {
            int row0 = wm * 32 + mt * 16 + (lane >> 2);
            int j0 = wn * 32 + nt * 8 + (lane & 3) * 2;
            float v0 = fmaxf(C[mt][nt][0] + B0s[j0], 0.0f);
            float v1 = fmaxf(C[mt][nt][1] + B0s[j0 + 1], 0.0f);
            float v2 = fmaxf(C[mt][nt][2] + B0s[j0], 0.0f);
            float v3 = fmaxf(C[mt][nt][3] + B0s[j0 + 1], 0.0f);
            store_h(sm, SM_XH0 + SWZ((u32)(row0 * 128 + j0 * 2)), v0, v1);
            store_h(sm, SM_XH0 + SWZ((u32)((row0 + 8) * 128 + j0 * 2)), v2, v3);
        }
    asm volatile("cp.async.wait_group 0;" ::: "memory");
    __syncthreads();

    // ================= LAYER 1 (K=64, N=64) =================
#pragma unroll
    for (int mt = 0; mt < 2; mt++)
#pragma unroll
        for (int nt = 0; nt < 4; nt++)
#pragma unroll
            for (int q = 0; q < 4; q++) C[mt][nt][q] = 0.0f;

#pragma unroll
    for (int kt = 0; kt < 4; kt++) {
        u32 a[2][4], bh0[4], bl0[4], bh1[4], bl1[4];
        u32 kx = (u32)(2 * kt + akoff);
        u32 o0 = arb0 + ((kx ^ ar70) << 4);
        u32 o1 = arb1 + ((kx ^ ar71) << 4);
        u32 wb = smb + SM_W1H + kt * 2048 + brow;
        ldmA(a[0], smb + SM_XH0 + o0);
        ldmA(a[1], smb + SM_XH0 + o1);
        ldmBT4(bh0, wb + bcol0);
        ldmBT4(bl0, wb + bcol0 + 8192);
        ldmBT4(bh1, wb + bcol1);
        ldmBT4(bl1, wb + bcol1 + 8192);
#pragma unroll
        for (int mt = 0; mt < 2; mt++)
#pragma unroll
            for (int sub = 0; sub < 2; sub++) {
                mma16816(C[mt][sub],     a[mt], &bh0[2 * sub]);
                mma16816(C[mt][2 + sub], a[mt], &bh1[2 * sub]);
            }
#pragma unroll
        for (int mt = 0; mt < 2; mt++)
#pragma unroll
            for (int sub = 0; sub < 2; sub++) {
                mma16816(C[mt][sub],     a[mt], &bl0[2 * sub]);
                mma16816(C[mt][2 + sub], a[mt], &bl1[2 * sub]);
            }
    }
    __syncthreads();   // done reading H before G overwrites the same panel

    // epilogue L1: bias+relu, fp16 store into XH0
#pragma unroll
    for (int mt = 0; mt < 2; mt++)
#pragma unroll
        for (int nt = 0; nt < 4; nt++) {
            int row0 = wm * 32 + mt * 16 + (lane >> 2);
            int j0 = wn * 32 + nt * 8 + (lane & 3) * 2;
            float v0 = fmaxf(C[mt][nt][0] + B1s[j0], 0.0f);
            float v1 = fmaxf(C[mt][nt][1] + B1s[j0 + 1], 0.0f);
            float v2 = fmaxf(C[mt][nt][2] + B1s[j0], 0.0f);
            float v3 = fmaxf(C[mt][nt][3] + B1s[j0 + 1], 0.0f);
            store_h(sm, SM_XH0 + SWZ((u32)(row0 * 128 + j0 * 2)), v0, v1);
            store_h(sm, SM_XH0 + SWZ((u32)((row0 + 8) * 128 + j0 * 2)), v2, v3);
        }
    __syncthreads();

    // ================= LAYER 2 (K=64, N=32) =================
    const u32 bcol2 = ((u32)((wn * 16 + bnh) * 2)) ^ bswz;
#pragma unroll
    for (int mt = 0; mt < 2; mt++)
#pragma unroll
        for (int nt = 0; nt < 2; nt++)
#pragma unroll
            for (int q = 0; q < 4; q++) C[mt][nt][q] = 0.0f;

#pragma unroll
    for (int kt = 0; kt < 4; kt++) {
        u32 a[2][4], bh[4], bl[4];
        u32 kx = (u32)(2 * kt + akoff);
        u32 o0 = arb0 + ((kx ^ ar70) << 4);
        u32 o1 = arb1 + ((kx ^ ar71) << 4);
        u32 addr = smb + SM_W2H + kt * 2048 + brow + bcol2;
        ldmA(a[0], smb + SM_XH0 + o0);
        ldmA(a[1], smb + SM_XH0 + o1);
        ldmBT4(bh, addr);
        ldmBT4(bl, addr + 8192);
#pragma unroll
        for (int mt = 0; mt < 2; mt++)
#pragma unroll
            for (int sub = 0; sub < 2; sub++) {
                mma16816(C[mt][sub], a[mt], &bh[2 * sub]);
                mma16816(C[mt][sub], a[mt], &bl[2 * sub]);
            }
    }

    // final epilogue: bias + shuffle-coalesced float4 scatter
#pragma unroll
    for (int mt = 0; mt < 2; mt++)
#pragma unroll
        for (int nt = 0; nt < 2; nt++) {
            int row0 = wm * 32 + mt * 16 + (lane >> 2);
            int q = lane & 3;
            int j0 = wn * 16 + nt * 8 + 2 * q;
            float a0 = C[mt][nt][0] + B2s[j0];
            float a1 = C[mt][nt][1] + B2s[j0 + 1];
            float b0 = C[mt][nt][2] + B2s[j0];
            float b1 = C[mt][nt][3] + B2s[j0 + 1];
            float pa0 = __shfl_xor_sync(0xFFFFFFFFu, a0, 1);
            float pa1 = __shfl_xor_sync(0xFFFFFFFFu, a1, 1);
            float pb0 = __shfl_xor_sync(0xFFFFFFFFu, b0, 1);
            float pb1 = __shfl_xor_sync(0xFFFFFFFFu, b1, 1);
            if (!(q & 1)) {
                int colb = wn * 16 + nt * 8 + 2 * q;
                if (row0 < cnt)
                    *(float4*)(out + (size_t)sids[row0] * DOUT + colb) =
                        make_float4(a0, a1, pa0, pa1);
                if (row0 + 8 < cnt)
                    *(float4*)(out + (size_t)sids[row0 + 8] * DOUT + colb) =
                        make_float4(b0, b1, pb0, pb1);
            }
        }
}

// ---------------- launch ----------------
extern "C" void kernel_launch(void* const* d_in, const int* in_sizes, int n_in,
                              void* d_out, int out_size) {
    (void)in_sizes; (void)n_in; (void)out_size;
    const int*   idxs      = (const int*)d_in[0];
    const float* positions = (const float*)d_in[1];
    const float* viewdirs  = (const float*)d_in[2];
    const float* features  = (const float*)d_in[3];
    const float* W0 = (const float*)d_in[4];
    const float* b0 = (const float*)d_in[5];
    const float* W1 = (const float*)d_in[6];
    const float* b1 = (const float*)d_in[7];
    const float* W2 = (const float*)d_in[8];
    const float* b2 = (const float*)d_in[9];
    float* out = (float*)d_out;

    cudaFuncSetAttribute(k_mlp, cudaFuncAttributeMaxDynamicSharedMemorySize, SMEM_BYTES);

    k_pre<<<NHB + 64, 256>>>(idxs, W0, b0, W1, b1, W2, b2);
    k_scan<<<1, 256>>>();
    k_scatter<<<NHB, 256>>>(idxs);
    k_mlp<<<MAXTILES, NT, SMEM_BYTES>>>(positions, viewdirs, features, out);
}

// round 17
// speedup vs baseline: 1.2653x; 1.0889x over previous
#include <cuda_runtime.h>
#include <cuda_fp16.h>

typedef unsigned int u32;

// ---------------- problem constants ----------------
#define NS    65536
#define KEXP  8
#define DIN   74
#define WID   64
#define DOUT  32
#define TILE  128
#define NT    256
#define MAXTILES (NS / TILE + KEXP)
#define NHB   256

// packed per-expert weight image (fp16 hi only):
// [0:8192)      W0H  [64 k][128B]   [8192:10240)  W0HT [16 k][128B]
// [10240:10880) biases fp32: B0[64] B1[64] B2[32]
// [10880:19072) W1H   [19072:27264) W2H
#define WPACK_BYTES 27264
#define WP_PH1      10880          // W0 hi + biases (contiguous)
#define WP_PH2_OFF  10880
#define WP_PH2      16384          // W1 + W2

// ---------------- smem layout (bytes) ----------------
#define SM_XH0  0                  // X/H/G fp16: [128 rows][128B] (k 0..63)
#define SM_XT   16384              // X tail: [128 rows][48B] (k 64..79)
#define SM_W0H  22528              // phase1 image [W0H|W0HT|biases]
#define SM_W0HT 30720
#define SM_B0   32768
#define SM_B1   33024
#define SM_B2   33280
#define SM_SIDS 33408
#define SMEM_BYTES 33920           // occ limited by regs (3 CTAs/SM @ 80 regs)
// phase2 overlay (XT + W0 dead after layer 0)
#define SM_W1H  16384
#define SM_W2H  24576

#define SWZ(off) ((off) ^ (((off) >> 3) & 0x70))

// ---------------- device scratch ----------------
__device__ int g_bhist[KEXP * NHB];
__device__ int g_bbase[KEXP * NHB];
__device__ int g_offs[KEXP + 1];
__device__ int g_order[NS];
__device__ __align__(16) char g_wpack[KEXP][WPACK_BYTES];

// ---------------- helpers ----------------
__device__ __forceinline__ u32 smem_u32(const void* p) {
    u32 a; asm("{ .reg .u64 t; cvta.to.shared.u64 t, %1; cvt.u32.u64 %0, t; }" : "=r"(a) : "l"(p));
    return a;
}
__device__ __forceinline__ void ldmA(u32 a[4], u32 addr) {
    asm volatile("ldmatrix.sync.aligned.m8n8.x4.shared.b16 {%0,%1,%2,%3}, [%4];"
                 : "=r"(a[0]), "=r"(a[1]), "=r"(a[2]), "=r"(a[3]) : "r"(addr));
}
__device__ __forceinline__ void ldmBT4(u32 b[4], u32 addr) {
    asm volatile("ldmatrix.sync.aligned.m8n8.x4.trans.shared.b16 {%0,%1,%2,%3}, [%4];"
                 : "=r"(b[0]), "=r"(b[1]), "=r"(b[2]), "=r"(b[3]) : "r"(addr));
}
__device__ __forceinline__ void mma16816(float c[4], const u32 a[4], const u32 b[2]) {
    asm volatile(
        "mma.sync.aligned.m16n8k16.row.col.f32.f16.f16.f32 "
        "{%0,%1,%2,%3}, {%4,%5,%6,%7}, {%8,%9}, {%0,%1,%2,%3};"
        : "+f"(c[0]), "+f"(c[1]), "+f"(c[2]), "+f"(c[3])
        : "r"(a[0]), "r"(a[1]), "r"(a[2]), "r"(a[3]), "r"(b[0]), "r"(b[1]));
}
__device__ __forceinline__ u32 hpack(__half a, __half b) {
    __half2 t(a, b);
    return *reinterpret_cast<u32*>(&t);
}
__device__ __forceinline__ void store_h(char* sm, u32 off, float v0, float v1) {
    *(u32*)(sm + off) = hpack(__float2half_rn(v0), __float2half_rn(v1));
}
__device__ __forceinline__ void split4h(float4 v, u32& h01, u32& h23) {
    h01 = hpack(__float2half_rn(v.x), __float2half_rn(v.y));
    h23 = hpack(__float2half_rn(v.z), __float2half_rn(v.w));
}
__device__ __forceinline__ void cp16(u32 dst_smem, const void* src) {
    asm volatile("cp.async.ca.shared.global [%0], [%1], 16;" :: "r"(dst_smem), "l"(src) : "memory");
}

// ---------------- merged hist + weight pre-pack ----------------
__global__ void k_pre(const int* __restrict__ idxs,
                      const float* __restrict__ W0g, const float* __restrict__ b0g,
                      const float* __restrict__ W1g, const float* __restrict__ b1g,
                      const float* __restrict__ W2g, const float* __restrict__ b2g) {
    if (blockIdx.x < NHB) {
        __shared__ int sh[KEXP];
        if (threadIdx.x < KEXP) sh[threadIdx.x] = 0;
        __syncthreads();
        atomicAdd(&sh[idxs[blockIdx.x * 256 + threadIdx.x]], 1);
        __syncthreads();
        if (threadIdx.x < KEXP) g_bhist[threadIdx.x * NHB + blockIdx.x] = sh[threadIdx.x];
        return;
    }
    int pb = blockIdx.x - NHB;
    int e = pb >> 3;
    int vt = (pb & 7) * 256 + threadIdx.x;
    char* dst = g_wpack[e];

    const float4* W0e = (const float4*)(W0g + e * DIN * WID);
    for (int i = vt; i < 80 * 16; i += 2048) {
        int k = i >> 4, cq = i & 15;
        float4 v = (k < DIN) ? W0e[k * 16 + cq] : make_float4(0.f, 0.f, 0.f, 0.f);
        u32 h01, h23; split4h(v, h01, h23);
        u32 base = 0;
        if (k >= 64) { base = 8192; k -= 64; }
        u32 off = base + SWZ((u32)(k * 128 + cq * 8));
        *(u32*)(dst + off) = h01; *(u32*)(dst + off + 4) = h23;
    }
    const float4* W1e = (const float4*)(W1g + e * WID * WID);
    for (int i = vt; i < 64 * 16; i += 2048) {
        int k = i >> 4, cq = i & 15;
        float4 v = W1e[k * 16 + cq];
        u32 h01, h23; split4h(v, h01, h23);
        u32 off = 10880 + SWZ((u32)(k * 128 + cq * 8));
        *(u32*)(dst + off) = h01; *(u32*)(dst + off + 4) = h23;
    }
    const float4* W2e = (const float4*)(W2g + e * WID * DOUT);
    for (int i = vt; i < 64 * 8; i += 2048) {
        int k = i >> 3, cq = i & 7;
        float4 v = W2e[k * 8 + cq];
        u32 h01, h23; split4h(v, h01, h23);
        u32 off = 19072 + SWZ((u32)(k * 128 + cq * 8));
        *(u32*)(dst + off) = h01; *(u32*)(dst + off + 4) = h23;
    }
    float* bd = (float*)(dst + 10240);
    for (int i = vt; i < 160; i += 2048)
        bd[i] = (i < 64) ? b0g[e * WID + i]
              : (i < 128) ? b1g[e * WID + i - 64]
              : b2g[e * DOUT + i - 128];
}

// ---------------- scan ----------------
__global__ void k_scan() {
    __shared__ int tot[KEXP];
    __shared__ int offs[KEXP];
    int w = threadIdx.x >> 5, lane = threadIdx.x & 31;
    int carry = 0;
    int excl[8];
#pragma unroll
    for (int c = 0; c < 8; c++) {
        int v = g_bhist[w * NHB + c * 32 + lane];
        int s = v;
#pragma unroll
        for (int d = 1; d < 32; d <<= 1) {
            int t = __shfl_up_sync(0xFFFFFFFFu, s, d);
            if (lane >= d) s += t;
        }
        excl[c] = carry + s - v;
        carry += __shfl_sync(0xFFFFFFFFu, s, 31);
    }
    if (lane == 0) tot[w] = carry;
    __syncthreads();
    if (threadIdx.x == 0) {
        int a = 0;
        for (int e = 0; e < KEXP; e++) { offs[e] = a; g_offs[e] = a; a += tot[e]; }
        g_offs[KEXP] = a;
    }
    __syncthreads();
    int o = offs[w];
#pragma unroll
    for (int c = 0; c < 8; c++) g_bbase[w * NHB + c * 32 + lane] = o + excl[c];
}

// ---------------- scatter ----------------
__global__ void k_scatter(const int* __restrict__ idxs) {
    __shared__ int s_loc[KEXP];
    __shared__ int s_base[KEXP];
    if (threadIdx.x < KEXP) {
        s_loc[threadIdx.x] = 0;
        s_base[threadIdx.x] = g_bbase[threadIdx.x * NHB + blockIdx.x];
    }
    __syncthreads();
    int i = blockIdx.x * 256 + threadIdx.x;
    int e = idxs[i];
    int r = atomicAdd(&s_loc[e], 1);
    g_order[s_base[e] + r] = i;
}

// ---------------- fused MMA MLP kernel (3 CTAs/SM, single-fp16 MMA) ----------------
__global__ void __launch_bounds__(NT, 3) k_mlp(
    const float* __restrict__ positions, const float* __restrict__ viewdirs,
    const float* __restrict__ features,
    float* __restrict__ out) {
    extern __shared__ char sm[];
    const u32 smb = smem_u32(sm);
    const int tid = threadIdx.x, lane = tid & 31, wid = tid >> 5;

    // blockIdx -> (expert, local tile)
    int e = -1, lt = 0;
    {
        int b = blockIdx.x, acc = 0;
#pragma unroll
        for (int i = 0; i < KEXP; i++) {
            int tiles = (g_offs[i + 1] - g_offs[i] + TILE - 1) / TILE;
            if (e < 0 && b < acc + tiles) { e = i; lt = b - acc; }
            acc += tiles;
        }
    }
    if (e < 0) return;
    const int base = g_offs[e] + lt * TILE;
    const int cnt = min(TILE, g_offs[e + 1] - base);

    int* sids = (int*)(sm + SM_SIDS);
    float* B0s = (float*)(sm + SM_B0);
    float* B1s = (float*)(sm + SM_B1);
    float* B2s = (float*)(sm + SM_B2);

    // ================= STAGING =================
    if (tid < TILE) {
        int n = g_order[base + min(tid, cnt - 1)];
        sids[tid] = n;
        const u32 rb = (u32)(tid * 128);
        const float4* f4 = (const float4*)(features + (size_t)n * 32);
#pragma unroll
        for (int i = 0; i < 8; i++) {
            float4 f = f4[i];
            store_h(sm, SM_XH0 + SWZ(rb + (u32)(8 * i)), f.x, f.y);
            store_h(sm, SM_XH0 + SWZ(rb + (u32)(8 * i + 4)), f.z, f.w);
        }
        {
            float p0 = positions[n * 3], p1 = positions[n * 3 + 1], p2 = positions[n * 3 + 2];
            float q0 = viewdirs[n * 3];
            float loc[16];
            loc[0] = p0; loc[1] = p1; loc[2] = p2;
#pragma unroll
            for (int s = 0; s < 2; s++) {
                float sc = (float)(1 << s);
                loc[3 + 3 * s] = __sinf(p0 * sc); loc[4 + 3 * s] = __sinf(p1 * sc); loc[5 + 3 * s] = __sinf(p2 * sc);
                loc[9 + 3 * s] = __cosf(p0 * sc); loc[10 + 3 * s] = __cosf(p1 * sc); loc[11 + 3 * s] = __cosf(p2 * sc);
            }
            loc[15] = q0;
#pragma unroll
            for (int j = 0; j < 8; j++)
                store_h(sm, SM_XH0 + SWZ(rb + (u32)((32 + 2 * j) * 2)), loc[2 * j], loc[2 * j + 1]);
        }
        {
            float q0 = viewdirs[n * 3], q1 = viewdirs[n * 3 + 1], q2 = viewdirs[n * 3 + 2];
            float loc[32];
            loc[0] = q1; loc[1] = q2;
#pragma unroll
            for (int s = 0; s < 4; s++) {
                float sc = (float)(1 << s);
                loc[2 + 3 * s] = __sinf(q0 * sc); loc[3 + 3 * s] = __sinf(q1 * sc); loc[4 + 3 * s] = __sinf(q2 * sc);
                loc[14 + 3 * s] = __cosf(q0 * sc); loc[15 + 3 * s] = __cosf(q1 * sc); loc[16 + 3 * s] = __cosf(q2 * sc);
            }
#pragma unroll
            for (int j = 26; j < 32; j++) loc[j] = 0.0f;
#pragma unroll
            for (int j = 0; j < 16; j++) {
                int k0 = 48 + 2 * j;
                if (k0 < 64)
                    store_h(sm, SM_XH0 + SWZ(rb + (u32)(k0 * 2)), loc[2 * j], loc[2 * j + 1]);
                else
                    store_h(sm, SM_XT + (u32)(tid * 48 + (k0 - 64) * 2), loc[2 * j], loc[2 * j + 1]);
            }
        }
    } else {
        // phase-1 weight copy: W0 hi + biases (10880 B, contiguous)
        int t2 = tid - TILE;
#pragma unroll
        for (int i = t2 * 16; i < WP_PH1; i += 128 * 16)
            cp16(smb + SM_W0H + i, g_wpack[e] + i);
        asm volatile("cp.async.commit_group;" ::: "memory");
        asm volatile("cp.async.wait_group 0;" ::: "memory");
    }
    __syncthreads();

    // fragment lane coordinates (warp grid: 4 M-groups x 2 N-groups)
    const int wm = wid >> 1, wn = wid & 1;
    const int amat = lane >> 3, amr = lane & 7;
    const int arow_off = ((amat & 1) << 3) + amr;
    const int akoff = amat >> 1;
    const int bk = ((lane >> 3) & 1) * 8 + (lane & 7);
    const int bnh = (lane >> 4) * 8;
    const u32 bswz = ((u32)(bk & 7)) << 4;
    const u32 brow = (u32)(bk * 128);
    const u32 bcol0 = ((u32)((wn * 32 + bnh) * 2)) ^ bswz;
    const u32 bcol1 = ((u32)((wn * 32 + 16 + bnh) * 2)) ^ bswz;

    const int arow0 = wm * 32 + arow_off;
    const int arow1 = arow0 + 16;
    const u32 arb0 = (u32)(arow0 * 128), arb1 = (u32)(arow1 * 128);
    const int ar70 = arow0 & 7, ar71 = arow1 & 7;

    float C[2][4][4];

    // ================= LAYER 0 (K=80, N=64) =================
#pragma unroll
    for (int mt = 0; mt < 2; mt++)
#pragma unroll
        for (int nt = 0; nt < 4; nt++)
#pragma unroll
            for (int q = 0; q < 4; q++) C[mt][nt][q] = 0.0f;

#pragma unroll
    for (int kt = 0; kt < 5; kt++) {
        u32 a[2][4], b0r[4], b1r[4];
        if (kt < 4) {
            u32 kx = (u32)(2 * kt + akoff);
            u32 o0 = arb0 + ((kx ^ ar70) << 4);
            u32 o1 = arb1 + ((kx ^ ar71) << 4);
            u32 wb = smb + SM_W0H + kt * 2048 + brow;
            ldmA(a[0], smb + SM_XH0 + o0);
            ldmA(a[1], smb + SM_XH0 + o1);
            ldmBT4(b0r, wb + bcol0);
            ldmBT4(b1r, wb + bcol1);
        } else {
            u32 o0 = (u32)(arow0 * 48 + (akoff << 4));
            u32 o1 = (u32)(arow1 * 48 + (akoff << 4));
            u32 wb = smb + SM_W0HT + brow;
            ldmA(a[0], smb + SM_XT + o0);
            ldmA(a[1], smb + SM_XT + o1);
            ldmBT4(b0r, wb + bcol0);
            ldmBT4(b1r, wb + bcol1);
        }
#pragma unroll
        for (int mt = 0; mt < 2; mt++)
#pragma unroll
            for (int sub = 0; sub < 2; sub++) {
                mma16816(C[mt][sub],     a[mt], &b0r[2 * sub]);
                mma16816(C[mt][2 + sub], a[mt], &b1r[2 * sub]);
            }
    }
    __syncthreads();   // all warps done reading X(+tail) and W0

    // phase-2 weight copy (W1 + W2 -> overlays dead XT/W0H), overlapped with epilogue
    {
        const char* src = g_wpack[e] + WP_PH2_OFF;
#pragma unroll
        for (int i = tid * 16; i < WP_PH2; i += NT * 16)
            cp16(smb + SM_W1H + i, src + i);
        asm volatile("cp.async.commit_group;" ::: "memory");
    }

    // epilogue L0: bias+relu, fp16 store into XH0
#pragma unroll
    for (int mt = 0; mt < 2; mt++)
#pragma unroll
        for (int nt = 0; nt < 4; nt++) {
            int row0 = wm * 32 + mt * 16 + (lane >> 2);
            int j0 = wn * 32 + nt * 8 + (lane & 3) * 2;
            float v0 = fmaxf(C[mt][nt][0] + B0s[j0], 0.0f);
            float v1 = fmaxf(C[mt][nt][1] + B0s[j0 + 1], 0.0f);
            float v2 = fmaxf(C[mt][nt][2] + B0s[j0], 0.0f);
            float v3 = fmaxf(C[mt][nt][3] + B0s[j0 + 1], 0.0f);
            store_h(sm, SM_XH0 + SWZ((u32)(row0 * 128 + j0 * 2)), v0, v1);
            store_h(sm, SM_XH0 + SWZ((u32)((row0 + 8) * 128 + j0 * 2)), v2, v3);
        }
    asm volatile("cp.async.wait_group 0;" ::: "memory");
    __syncthreads();

    // ================= LAYER 1 (K=64, N=64) =================
#pragma unroll
    for (int mt = 0; mt < 2; mt++)
#pragma unroll
        for (int nt = 0; nt < 4; nt++)
#pragma unroll
            for (int q = 0; q < 4; q++) C[mt][nt][q] = 0.0f;

#pragma unroll
    for (int kt = 0; kt < 4; kt++) {
        u32 a[2][4], b0r[4], b1r[4];
        u32 kx = (u32)(2 * kt + akoff);
        u32 o0 = arb0 + ((kx ^ ar70) << 4);
        u32 o1 = arb1 + ((kx ^ ar71) << 4);
        u32 wb = smb + SM_W1H + kt * 2048 + brow;
        ldmA(a[0], smb + SM_XH0 + o0);
        ldmA(a[1], smb + SM_XH0 + o1);
        ldmBT4(b0r, wb + bcol0);
        ldmBT4(b1r, wb + bcol1);
#pragma unroll
        for (int mt = 0; mt < 2; mt++)
#pragma unroll
            for (int sub = 0; sub < 2; sub++) {
                mma16816(C[mt][sub],     a[mt], &b0r[2 * sub]);
                mma16816(C[mt][2 + sub], a[mt], &b1r[2 * sub]);
            }
    }
    __syncthreads();   // done reading H before G overwrites the same panel

    // epilogue L1: bias+relu, fp16 store into XH0
#pragma unroll
    for (int mt = 0; mt < 2; mt++)
#pragma unroll
        for (int nt = 0; nt < 4; nt++) {
            int row0 = wm * 32 + mt * 16 + (lane >> 2);
            int j0 = wn * 32 + nt * 8 + (lane & 3) * 2;
            float v0 = fmaxf(C[mt][nt][0] + B1s[j0], 0.0f);
            float v1 = fmaxf(C[mt][nt][1] + B1s[j0 + 1], 0.0f);
            float v2 = fmaxf(C[mt][nt][2] + B1s[j0], 0.0f);
            float v3 = fmaxf(C[mt][nt][3] + B1s[j0 + 1], 0.0f);
            store_h(sm, SM_XH0 + SWZ((u32)(row0 * 128 + j0 * 2)), v0, v1);
            store_h(sm, SM_XH0 + SWZ((u32)((row0 + 8) * 128 + j0 * 2)), v2, v3);
        }
    __syncthreads();

    // ================= LAYER 2 (K=64, N=32) =================
    const u32 bcol2 = ((u32)((wn * 16 + bnh) * 2)) ^ bswz;
#pragma unroll
    for (int mt = 0; mt < 2; mt++)
#pragma unroll
        for (int nt = 0; nt < 2; nt++)
#pragma unroll
            for (int q = 0; q < 4; q++) C[mt][nt][q] = 0.0f;

#pragma unroll
    for (int kt = 0; kt < 4; kt++) {
        u32 a[2][4], br[4];
        u32 kx = (u32)(2 * kt + akoff);
        u32 o0 = arb0 + ((kx ^ ar70) << 4);
        u32 o1 = arb1 + ((kx ^ ar71) << 4);
        ldmA(a[0], smb + SM_XH0 + o0);
        ldmA(a[1], smb + SM_XH0 + o1);
        ldmBT4(br, smb + SM_W2H + kt * 2048 + brow + bcol2);
#pragma unroll
        for (int mt = 0; mt < 2; mt++)
#pragma unroll
            for (int sub = 0; sub < 2; sub++)
                mma16816(C[mt][sub], a[mt], &br[2 * sub]);
    }

    // final epilogue: bias + shuffle-coalesced float4 scatter
#pragma unroll
    for (int mt = 0; mt < 2; mt++)
#pragma unroll
        for (int nt = 0; nt < 2; nt++) {
            int row0 = wm * 32 + mt * 16 + (lane >> 2);
            int q = lane & 3;
            int j0 = wn * 16 + nt * 8 + 2 * q;
            float a0 = C[mt][nt][0] + B2s[j0];
            float a1 = C[mt][nt][1] + B2s[j0 + 1];
            float b0 = C[mt][nt][2] + B2s[j0];
            float b1 = C[mt][nt][3] + B2s[j0 + 1];
            float pa0 = __shfl_xor_sync(0xFFFFFFFFu, a0, 1);
            float pa1 = __shfl_xor_sync(0xFFFFFFFFu, a1, 1);
            float pb0 = __shfl_xor_sync(0xFFFFFFFFu, b0, 1);
            float pb1 = __shfl_xor_sync(0xFFFFFFFFu, b1, 1);
            if (!(q & 1)) {
                int colb = wn * 16 + nt * 8 + 2 * q;
                if (row0 < cnt)
                    *(float4*)(out + (size_t)sids[row0] * DOUT + colb) =
                        make_float4(a0, a1, pa0, pa1);
                if (row0 + 8 < cnt)
                    *(float4*)(out + (size_t)sids[row0 + 8] * DOUT + colb) =
                        make_float4(b0, b1, pb0, pb1);
            }
        }
}

// ---------------- launch ----------------
extern "C" void kernel_launch(void* const* d_in, const int* in_sizes, int n_in,
                              void* d_out, int out_size) {
    (void)in_sizes; (void)n_in; (void)out_size;
    const int*   idxs      = (const int*)d_in[0];
    const float* positions = (const float*)d_in[1];
    const float* viewdirs  = (const float*)d_in[2];
    const float* features  = (const float*)d_in[3];
    const float* W0 = (const float*)d_in[4];
    const float* b0 = (const float*)d_in[5];
    const float* W1 = (const float*)d_in[6];
    const float* b1 = (const float*)d_in[7];
    const float* W2 = (const float*)d_in[8];
    const float* b2 = (const float*)d_in[9];
    float* out = (float*)d_out;

    cudaFuncSetAttribute(k_mlp, cudaFuncAttributeMaxDynamicSharedMemorySize, SMEM_BYTES);

    k_pre<<<NHB + 64, 256>>>(idxs, W0, b0, W1, b1, W2, b2);
    k_scan<<<1, 256>>>();
    k_scatter<<<NHB, 256>>>(idxs);
    k_mlp<<<MAXTILES, NT, SMEM_BYTES>>>(positions, viewdirs, features, out);
}